// round 4
// baseline (speedup 1.0000x reference)
#include <cuda_runtime.h>
#include <cuda_bf16.h>

// WaveletTransformLayer: x (B=128, T=2048, F=32) f32.
// Per (b,f): d1 (2047) | d2 (2044) | d3 (2037) | ma3 (2037), each / T.
//   d1[t]  = (x[t+1]-x[t])/2
//   ma2'   = 8*ma2: ma2'[t] = x[t] + 2(x[t+1]+x[t+2]+x[t+3]) + x[t+4] = pp[t]+pp[t+1]+pp[t+2]+pp[t+3]
//   d2[t]  = (x[t+3]+x[t+4])/2 - ma2[t] = pp[t+3]/2 - ma2'[t]/8
//   ma3[t] = (1/8) sum_{j=0..7} ma2[t+j] = S[t]/64,  S = sum8 of ma2'
//   d3[t]  = ma2[t+7] - ma3[t]
// Bottleneck analysis (R3): LSU-issue bound on scalar STG.32. This version:
//   - f-major smem (pitch 192 + 4-feature skew): fill STS.32 and compute LDS.128 conflict-free
//   - each thread computes 4 consecutive t per (f,seg) -> STG.128 stores
//   - computed at shift aB=(f+3)%4 (warp-uniform, templated) so d2/d3 stores are 16B-aligned;
//     d1/ma3 re-aligned with a single shfl.up rotation; edges via predicated scalars.

#define T_LEN   2048
#define F_DIM   32
#define TT      128
#define NTILES  (T_LEN / TT)      // 16
#define PT      192               // smem pitch (floats), multiple of 32
#define LOADT   148               // t range [t0-4, t0+144)
#define OUT_PER_F 8165
#define SEG1    2047
#define SEG2    4091
#define SEG3    6128
#define LIM1    2047
#define LIM2    2044
#define LIM3    2037

__device__ __forceinline__ void load_v(const float* __restrict__ rb, int l, float* v) {
    #pragma unroll
    for (int c = 0; c < 5; ++c) {
        float4 q = *(const float4*)(rb + 4 * l + 4 * c);   // conflict-free LDS.128
        v[4*c + 0] = q.x; v[4*c + 1] = q.y; v[4*c + 2] = q.z; v[4*c + 3] = q.w;
    }
}

// Compute 4 outputs per stream for t = (v-index BASE) .. BASE+3 relative to v[0].
template<int BASE>
__device__ __forceinline__ void compute16(const float* __restrict__ v,
                                          float* d1, float* d2, float* d3, float* m3) {
    const float inv   = 1.0f / 2048.0f;
    const float inv2  = inv * 0.5f;
    const float inv8  = inv * 0.125f;
    const float inv64 = inv * 0.015625f;

    float pp[14];
    #pragma unroll
    for (int i = 0; i < 14; ++i) pp[i] = v[BASE + i] + v[BASE + i + 1];

    float m2[11];
    #pragma unroll
    for (int i = 0; i < 11; ++i) m2[i] = (pp[i] + pp[i + 1]) + (pp[i + 2] + pp[i + 3]);

    float S[4];
    S[0] = ((m2[0] + m2[1]) + (m2[2] + m2[3])) + ((m2[4] + m2[5]) + (m2[6] + m2[7]));
    S[1] = S[0] - m2[0] + m2[8];
    S[2] = S[1] - m2[1] + m2[9];
    S[3] = S[2] - m2[2] + m2[10];

    #pragma unroll
    for (int k = 0; k < 4; ++k) {
        d1[k] = (v[BASE + k + 1] - v[BASE + k]) * inv2;
        d2[k] = pp[k + 3] * inv2 - m2[k] * inv8;
        d3[k] = m2[k + 7] * inv8 - S[k] * inv64;
        m3[k] = S[k] * inv64;
    }
}

template<int W>
__device__ __forceinline__ void fast_warp(const float* __restrict__ xs, int l,
                                          float* __restrict__ outb, int t0) {
    constexpr int AB   = (W + 3) & 3;   // shift so d2/d3 stores are aligned
    constexpr int BASE = 4 - AB;
    #pragma unroll 1
    for (int j = 0; j < 8; ++j) {
        const int f = 4 * j + W;
        const float* rb = xs + f * PT + j * 4;   // skew = (f>>2)*4 = j*4
        float v[20];
        load_v(rb, l, v);
        float d1[4], d2[4], d3[4], m3[4];
        compute16<BASE>(v, d1, d2, d3, m3);

        float* of = outb + (size_t)f * OUT_PER_F;
        const int tg = t0 + 4 * l - AB;

        *(float4*)(of + SEG1 + tg) = make_float4(d2[0], d2[1], d2[2], d2[3]);
        *(float4*)(of + SEG2 + tg) = make_float4(d3[0], d3[1], d3[2], d3[3]);

        float p1 = __shfl_up_sync(0xffffffffu, d1[3], 1);
        float p3 = __shfl_up_sync(0xffffffffu, m3[3], 1);
        if (l > 0) {
            *(float4*)(of + tg - 1)        = make_float4(p1, d1[0], d1[1], d1[2]);
            *(float4*)(of + SEG3 + tg - 1) = make_float4(p3, m3[0], m3[1], m3[2]);
        } else {
            of[tg]            = d1[0]; of[tg + 1]            = d1[1]; of[tg + 2]            = d1[2];
            of[SEG3 + tg]     = m3[0]; of[SEG3 + tg + 1]     = m3[1]; of[SEG3 + tg + 2]     = m3[2];
        }
        if (l == 31) {
            of[tg + 3]        = d1[3];
            of[SEG3 + tg + 3] = m3[3];
        }
    }
}

__device__ __forceinline__ void slow_warp(const float* __restrict__ xs, int w, int l,
                                          float* __restrict__ outb, int t0) {
    #pragma unroll 1
    for (int j = 0; j < 8; ++j) {
        const int f = 4 * j + w;
        const float* rb = xs + f * PT + j * 4;
        float v[20];
        load_v(rb, l, v);
        float d1[4], d2[4], d3[4], m3[4];
        compute16<4>(v, d1, d2, d3, m3);   // shift 0: t = t0 + 4l + k
        float* of = outb + (size_t)f * OUT_PER_F;
        #pragma unroll
        for (int k = 0; k < 4; ++k) {
            int t = t0 + 4 * l + k;
            if (t < LIM1) of[t] = d1[k];
            if (t < LIM2) of[SEG1 + t] = d2[k];
            if (t < LIM3) { of[SEG2 + t] = d3[k]; of[SEG3 + t] = m3[k]; }
        }
        if (l == 0) {   // left extension t0-4..t0-1 (covers fast-neighbor gap at tile 15)
            compute16<0>(v, d1, d2, d3, m3);
            #pragma unroll
            for (int k = 0; k < 4; ++k) {
                int t = t0 - 4 + k;
                if (t >= 0) {
                    if (t < LIM1) of[t] = d1[k];
                    if (t < LIM2) of[SEG1 + t] = d2[k];
                    if (t < LIM3) { of[SEG2 + t] = d3[k]; of[SEG3 + t] = m3[k]; }
                }
            }
        }
    }
}

__global__ __launch_bounds__(128, 6)
void wavelet_kernel(const float* __restrict__ x, float* __restrict__ out) {
    __shared__ float xs[F_DIM * PT];   // 24576 B, f-major with skew

    const int tile = blockIdx.x;       // 0..15
    const int b    = blockIdx.y;       // 0..127
    const int t0   = tile * TT;
    const int tid  = threadIdx.x;      // 0..127

    // ---- Fill: LDG.128 (t-major) -> 4x STS.32 transpose into f-major skewed rows ----
    const float4* gsrc = (const float4*)(x + (size_t)b * (T_LEN * F_DIM)) + (t0 - 4) * 8;
    #pragma unroll
    for (int k = 0; k < 10; ++k) {
        int i = tid + k * 128;
        if (i < LOADT * 8) {           // 1184 vec4s
            int tt = i >> 3;           // t_local 0..147  (t = t0-4+tt)
            int f4 = (i & 7) << 2;
            int tg = t0 - 4 + tt;
            float4 vv = make_float4(0.f, 0.f, 0.f, 0.f);
            if (tg >= 0 && tg < T_LEN) vv = gsrc[i];
            float* d = xs + f4 * PT + ((f4 >> 2) & 7) * 4 + tt;
            d[0]      = vv.x;
            d[PT]     = vv.y;
            d[2 * PT] = vv.z;
            d[3 * PT] = vv.w;
        }
    }
    __syncthreads();

    const int w = tid >> 5;
    const int l = tid & 31;
    float* outb = out + (size_t)b * (F_DIM * OUT_PER_F);

    if (tile != 0 && tile != NTILES - 1) {
        if      (w == 0) fast_warp<0>(xs, l, outb, t0);
        else if (w == 1) fast_warp<1>(xs, l, outb, t0);
        else if (w == 2) fast_warp<2>(xs, l, outb, t0);
        else             fast_warp<3>(xs, l, outb, t0);
    } else {
        slow_warp(xs, w, l, outb, t0);
    }
}

extern "C" void kernel_launch(void* const* d_in, const int* in_sizes, int n_in,
                              void* d_out, int out_size) {
    const float* x = (const float*)d_in[0];
    float* out = (float*)d_out;
    dim3 grid(NTILES, 128);   // 16 x 128 = 2048 blocks
    wavelet_kernel<<<grid, 128>>>(x, out);
}

// round 5
// speedup vs baseline: 1.1545x; 1.1545x over previous
#include <cuda_runtime.h>
#include <cuda_bf16.h>

// WaveletTransformLayer: x (B=128, T=2048, F=32) f32.
// Per (b,f): d1 (2047) | d2 (2044) | d3 (2037) | ma3 (2037), each / T.
// Collapsed FIR taps over x[t..t+11]:
//   d1[t] = (x1-x0)/2 ; ma2 = [1,2,2,2,1]/8 ; ma3 = [1,3,5,7,8,8,8,8,7,5,3,1]/64
//   d2[t] = (x3+x4)/2 - ma2[t] ; d3[t] = ma2[t+7] - ma3[t]
//
// R5 thesis: latency-bound, so maximize occupancy. Low-register scalar pipeline
// (R1-style), 12 blocks/SM via __launch_bounds__(128,12) -> 75% theoretical occ.

#define T_LEN   2048
#define F_DIM   32
#define TT      128
#define NTILES  (T_LEN / TT)     // 16
#define HALO    12
#define LOADT   (TT + HALO)      // 140
#define PITCH   33               // conflict-free for STS.32 fill and LDS.32 compute
#define OUT_PER_F 8165
#define SEG1    2047
#define SEG2    4091
#define SEG3    6128
#define LIM1    2047
#define LIM2    2044
#define LIM3    2037

__global__ __launch_bounds__(128, 12)
void wavelet_kernel(const float* __restrict__ x, float* __restrict__ out) {
    __shared__ float xs[LOADT * PITCH];   // 140*33*4 = 18480 B

    const int tile = blockIdx.x;          // 0..15
    const int b    = blockIdx.y;          // 0..127
    const int t0   = tile * TT;
    const int tid  = threadIdx.x;         // 0..127

    // ---- Fill: LDG.128 (t-major, f contiguous) -> 4x STS.32, conflict-free ----
    const float4* gsrc = (const float4*)(x + (size_t)b * (T_LEN * F_DIM)
                                           + (size_t)t0 * F_DIM);
    if (tile != NTILES - 1) {
        #pragma unroll
        for (int k = 0; k < 9; ++k) {
            int i = tid + k * 128;
            if (i < LOADT * 8) {          // 1120 vec4s
                int tt = i >> 3;
                int f4 = (i & 7) << 2;
                float4 v = gsrc[i];
                float* d = &xs[tt * PITCH + f4];
                d[0] = v.x; d[1] = v.y; d[2] = v.z; d[3] = v.w;
            }
        }
    } else {
        #pragma unroll
        for (int k = 0; k < 9; ++k) {
            int i = tid + k * 128;
            if (i < LOADT * 8) {
                int tt = i >> 3;
                int f4 = (i & 7) << 2;
                float4 v = make_float4(0.f, 0.f, 0.f, 0.f);
                if (t0 + tt < T_LEN) v = gsrc[i];
                float* d = &xs[tt * PITCH + f4];
                d[0] = v.x; d[1] = v.y; d[2] = v.z; d[3] = v.w;
            }
        }
    }
    __syncthreads();

    // ---- Compute: thread = t (lane-contiguous -> coalesced stores), loop f ----
    const int t  = tid;
    const int tg = t0 + t;
    float* outb = out + (size_t)b * (F_DIM * OUT_PER_F);

    const float inv   = 1.0f / 2048.0f;
    const float inv2  = inv * 0.5f;
    const float inv8  = inv * 0.125f;
    const float inv64 = inv * 0.015625f;

    if (t0 + TT <= LIM3) {   // tiles 0..14: all stores unconditional
        #pragma unroll 2
        for (int f = 0; f < F_DIM; ++f) {
            const float* s = xs + t * PITCH + f;
            float x0  = s[0 * PITCH],  x1 = s[1 * PITCH],  x2  = s[2 * PITCH];
            float x3  = s[3 * PITCH],  x4 = s[4 * PITCH],  x5  = s[5 * PITCH];
            float x6  = s[6 * PITCH],  x7 = s[7 * PITCH],  x8  = s[8 * PITCH];
            float x9  = s[9 * PITCH], x10 = s[10 * PITCH], x11 = s[11 * PITCH];

            float d1  = (x1 - x0) * inv2;
            float m2a = x0 + x4 + 2.0f * (x1 + x2 + x3);
            float d2  = (x3 + x4) * inv2 - m2a * inv8;
            float m2b = x7 + x11 + 2.0f * (x8 + x9 + x10);
            float m3  = (x0 + x11) + 3.0f * (x1 + x10) + 5.0f * (x2 + x9)
                      + 7.0f * (x3 + x8) + 8.0f * (x4 + x5 + x6 + x7);
            float d3  = m2b * inv8 - m3 * inv64;
            float ma3 = m3 * inv64;

            float* of = outb + (size_t)f * OUT_PER_F;
            of[tg]        = d1;
            of[SEG1 + tg] = d2;
            of[SEG2 + tg] = d3;
            of[SEG3 + tg] = ma3;
        }
    } else {                 // tile 15: predicated stores
        const bool w1 = (tg < LIM1);
        const bool w2 = (tg < LIM2);
        const bool w3 = (tg < LIM3);
        #pragma unroll 2
        for (int f = 0; f < F_DIM; ++f) {
            const float* s = xs + t * PITCH + f;
            float x0  = s[0 * PITCH],  x1 = s[1 * PITCH],  x2  = s[2 * PITCH];
            float x3  = s[3 * PITCH],  x4 = s[4 * PITCH],  x5  = s[5 * PITCH];
            float x6  = s[6 * PITCH],  x7 = s[7 * PITCH],  x8  = s[8 * PITCH];
            float x9  = s[9 * PITCH], x10 = s[10 * PITCH], x11 = s[11 * PITCH];

            float d1  = (x1 - x0) * inv2;
            float m2a = x0 + x4 + 2.0f * (x1 + x2 + x3);
            float d2  = (x3 + x4) * inv2 - m2a * inv8;
            float m2b = x7 + x11 + 2.0f * (x8 + x9 + x10);
            float m3  = (x0 + x11) + 3.0f * (x1 + x10) + 5.0f * (x2 + x9)
                      + 7.0f * (x3 + x8) + 8.0f * (x4 + x5 + x6 + x7);
            float d3  = m2b * inv8 - m3 * inv64;
            float ma3 = m3 * inv64;

            float* of = outb + (size_t)f * OUT_PER_F;
            if (w1) of[tg]        = d1;
            if (w2) of[SEG1 + tg] = d2;
            if (w3) {
                of[SEG2 + tg] = d3;
                of[SEG3 + tg] = ma3;
            }
        }
    }
}

extern "C" void kernel_launch(void* const* d_in, const int* in_sizes, int n_in,
                              void* d_out, int out_size) {
    const float* x = (const float*)d_in[0];
    float* out = (float*)d_out;
    dim3 grid(NTILES, 128);   // 16 x 128 = 2048 blocks
    wavelet_kernel<<<grid, 128>>>(x, out);
}